// round 8
// baseline (speedup 1.0000x reference)
#include <cuda_runtime.h>
#include <cuda_bf16.h>
#include <math.h>
#include <stdint.h>

#define kNA 8192
#define kNT 8192
#define kD  256
#define kH  128
#define INV_EPS 10.0f
#define QSCALE 4.8828125e-4f   /* 1/2048 */
#define NEGINF -3.402823466e38f

__device__ float g_q[kNA * kD];
__device__ float g_k[kNT * kD];
__device__ float g_h[kNA * kH];
__device__ float g_logits[kNA];
__device__ float g_logb[kNA];
__device__ float g_f[kNA];
__device__ float g_g[kNT];
__device__ short g_Mhi[67108864];          // 128 MB: i24 >> 8
__device__ unsigned char g_Mlo[67108864];  //  64 MB: i24 & 0xFF
__device__ float g_pm[32 * kNT];
__device__ float g_ps[32 * kNT];
__device__ int   g_cnt[16];
__device__ __nv_bfloat16 g_qs[3][kNA * kD];
__device__ __nv_bfloat16 g_ks[3][kNT * kD];

// ---------------- PTX helpers ----------------
__device__ __forceinline__ uint32_t smem_u32(const void* p) {
    uint32_t a;
    asm("{ .reg .u64 t; cvta.to.shared.u64 t, %1; cvt.u32.u64 %0, t; }" : "=r"(a) : "l"(p));
    return a;
}
__device__ __forceinline__ void cp16(uint32_t s, const void* g) {
    asm volatile("cp.async.cg.shared.global [%0], [%1], 16;" :: "r"(s), "l"(g));
}
__device__ __forceinline__ void ldm4(uint32_t& r0, uint32_t& r1, uint32_t& r2,
                                     uint32_t& r3, uint32_t a) {
    asm volatile("ldmatrix.sync.aligned.m8n8.x4.shared.b16 {%0,%1,%2,%3}, [%4];"
                 : "=r"(r0), "=r"(r1), "=r"(r2), "=r"(r3) : "r"(a));
}
__device__ __forceinline__ void mma16816(float* c, const uint32_t* a, const uint32_t* b) {
    asm volatile("mma.sync.aligned.m16n8k16.row.col.f32.bf16.bf16.f32 "
                 "{%0,%1,%2,%3}, {%4,%5,%6,%7}, {%8,%9}, {%0,%1,%2,%3};"
                 : "+f"(c[0]), "+f"(c[1]), "+f"(c[2]), "+f"(c[3])
                 : "r"(a[0]), "r"(a[1]), "r"(a[2]), "r"(a[3]), "r"(b[0]), "r"(b[1]));
}

// decode 8 consecutive 24-bit values + add g (shift-based sign extension)
__device__ __forceinline__ void dec8(int4 w, int2 b, const float* gv, float* x) {
    int h0 = (w.x << 16) >> 16, h1 = w.x >> 16;
    int h2 = (w.y << 16) >> 16, h3 = w.y >> 16;
    int h4 = (w.z << 16) >> 16, h5 = w.z >> 16;
    int h6 = (w.w << 16) >> 16, h7 = w.w >> 16;
    int l0 = b.x & 255, l1 = (b.x >> 8) & 255;
    int l2 = (b.x >> 16) & 255, l3 = (int)(((unsigned)b.x) >> 24);
    int l4 = b.y & 255, l5 = (b.y >> 8) & 255;
    int l6 = (b.y >> 16) & 255, l7 = (int)(((unsigned)b.y) >> 24);
    x[0] = fmaf((float)(h0 * 256 + l0), QSCALE, gv[0]);
    x[1] = fmaf((float)(h1 * 256 + l1), QSCALE, gv[1]);
    x[2] = fmaf((float)(h2 * 256 + l2), QSCALE, gv[2]);
    x[3] = fmaf((float)(h3 * 256 + l3), QSCALE, gv[3]);
    x[4] = fmaf((float)(h4 * 256 + l4), QSCALE, gv[4]);
    x[5] = fmaf((float)(h5 * 256 + l5), QSCALE, gv[5]);
    x[6] = fmaf((float)(h6 * 256 + l6), QSCALE, gv[6]);
    x[7] = fmaf((float)(h7 * 256 + l7), QSCALE, gv[7]);
}

// ---------------- small SIMT GEMM (q,k,h) ----------------
template<bool RELU>
__global__ void __launch_bounds__(256, 2) gemm128_kernel(
    const float* __restrict__ A, const float* __restrict__ B,
    const float* __restrict__ bias, float* __restrict__ C, int N, int K)
{
    __shared__ float As[16][130];
    __shared__ float Bs[16][130];
    const int tid = threadIdx.x, tx = tid & 15, ty = tid >> 4;
    const int m0 = blockIdx.y * 128, n0 = blockIdx.x * 128;
    const int lr = tid >> 2, lk = (tid & 3) << 2;
    float acc[8][8];
#pragma unroll
    for (int i = 0; i < 8; i++)
#pragma unroll
        for (int j = 0; j < 8; j++) acc[i][j] = 0.f;
    for (int k0 = 0; k0 < K; k0 += 16) {
#pragma unroll
        for (int h = 0; h < 2; h++) {
            int row = lr + h * 64;
            float4 v = *reinterpret_cast<const float4*>(A + (size_t)(m0 + row) * K + k0 + lk);
            As[lk + 0][row] = v.x; As[lk + 1][row] = v.y;
            As[lk + 2][row] = v.z; As[lk + 3][row] = v.w;
        }
        {
            int kk = tid >> 4, nx = (tid & 15) << 2;
#pragma unroll
            for (int h = 0; h < 2; h++) {
                int n = nx + h * 64;
                float4 v = *reinterpret_cast<const float4*>(B + (size_t)(k0 + kk) * N + n0 + n);
                Bs[kk][n + 0] = v.x; Bs[kk][n + 1] = v.y;
                Bs[kk][n + 2] = v.z; Bs[kk][n + 3] = v.w;
            }
        }
        __syncthreads();
#pragma unroll
        for (int kk = 0; kk < 16; kk++) {
            float a[8], b[8];
#pragma unroll
            for (int e = 0; e < 4; e++) {
                a[e] = As[kk][ty * 4 + e];     a[e + 4] = As[kk][ty * 4 + 64 + e];
                b[e] = Bs[kk][tx * 4 + e];     b[e + 4] = Bs[kk][tx * 4 + 64 + e];
            }
#pragma unroll
            for (int i = 0; i < 8; i++)
#pragma unroll
                for (int j = 0; j < 8; j++) acc[i][j] += a[i] * b[j];
        }
        __syncthreads();
    }
#pragma unroll
    for (int i = 0; i < 8; i++) {
        int row = m0 + ty * 4 + (i < 4 ? i : i - 4 + 64);
#pragma unroll
        for (int jh = 0; jh < 2; jh++) {
            int col = n0 + tx * 4 + jh * 64;
            float4 v;
            v.x = acc[i][jh * 4 + 0] + bias[col + 0];
            v.y = acc[i][jh * 4 + 1] + bias[col + 1];
            v.z = acc[i][jh * 4 + 2] + bias[col + 2];
            v.w = acc[i][jh * 4 + 3] + bias[col + 3];
            if (RELU) {
                v.x = fmaxf(v.x, 0.f); v.y = fmaxf(v.y, 0.f);
                v.z = fmaxf(v.z, 0.f); v.w = fmaxf(v.w, 0.f);
            }
            *reinterpret_cast<float4*>(C + (size_t)row * N + col) = v;
        }
    }
}

// ---------------- bf16x3 split ----------------
__global__ void __launch_bounds__(256) split3_kernel(
    const float* __restrict__ x, __nv_bfloat16* __restrict__ h0,
    __nv_bfloat16* __restrict__ l0, __nv_bfloat16* __restrict__ l1)
{
    int i = (blockIdx.x * 256 + threadIdx.x) * 4;
    float4 v = *reinterpret_cast<const float4*>(x + i);
    float vs[4] = {v.x, v.y, v.z, v.w};
    __nv_bfloat16 hh[4], ll[4], mm[4];
#pragma unroll
    for (int c = 0; c < 4; c++) {
        __nv_bfloat16 h = __float2bfloat16(vs[c]);
        float r = vs[c] - __bfloat162float(h);
        __nv_bfloat16 l = __float2bfloat16(r);
        hh[c] = h; ll[c] = l; mm[c] = __float2bfloat16(r - __bfloat162float(l));
    }
    *reinterpret_cast<__nv_bfloat162*>(h0 + i)     = __nv_bfloat162{hh[0], hh[1]};
    *reinterpret_cast<__nv_bfloat162*>(h0 + i + 2) = __nv_bfloat162{hh[2], hh[3]};
    *reinterpret_cast<__nv_bfloat162*>(l0 + i)     = __nv_bfloat162{ll[0], ll[1]};
    *reinterpret_cast<__nv_bfloat162*>(l0 + i + 2) = __nv_bfloat162{ll[2], ll[3]};
    *reinterpret_cast<__nv_bfloat162*>(l1 + i)     = __nv_bfloat162{mm[0], mm[1]};
    *reinterpret_cast<__nv_bfloat162*>(l1 + i + 2) = __nv_bfloat162{mm[2], mm[3]};
}

// ---------------- mma.sync GEMM -> quantized M (24-bit) ----------------
#define CH_BYTES 20480
#define MG_SMEM  40960

__device__ __forceinline__ void ld_chunk(int c, int m0, int n0, uint32_t sb, int tid)
{
    int term = c >> 3, kc = (c & 7) * 32;
    int at = (0x850 >> (term * 2)) & 3;   // {0,0,1,1,0,2}
    int bt = (0x244 >> (term * 2)) & 3;   // {0,1,0,1,2,0}
    const __nv_bfloat16* A = &g_qs[at][0] + (size_t)m0 * kD + kc;
    const __nv_bfloat16* B = &g_ks[bt][0] + (size_t)n0 * kD + kc;
    uint32_t base = sb + (c & 1) * CH_BYTES;
#pragma unroll
    for (int i = 0; i < 4; i++) {
        int idx = i * 256 + tid;
        int mat = idx >> 9, j = idx & 511;
        int row = j >> 2, seg = j & 3;
        const __nv_bfloat16* src = (mat ? B : A) + (size_t)row * kD + seg * 8;
        cp16(base + mat * 10240 + row * 80 + seg * 16, src);
    }
    asm volatile("cp.async.commit_group;" ::: "memory");
}

__global__ void __launch_bounds__(256) mgemm_kernel()
{
    extern __shared__ char smem[];
    uint32_t sb = smem_u32(smem);
    const int tid = threadIdx.x, wid = tid >> 5, lane = tid & 31;
    const int wm = wid & 1, wn = wid >> 1;
    const int m0 = blockIdx.y * 128, n0 = blockIdx.x * 128;

    float acc[4][4][4];
#pragma unroll
    for (int i = 0; i < 4; i++)
#pragma unroll
        for (int j = 0; j < 4; j++)
#pragma unroll
            for (int e = 0; e < 4; e++) acc[i][j][e] = 0.f;

    const int a_row = lane & 15;
    const int a_kb  = (lane >> 4) * 16;
    const int b_row = (lane & 7) + ((lane >> 4) << 3);
    const int b_kb  = ((lane >> 3) & 1) * 16;

    ld_chunk(0, m0, n0, sb, tid);
#pragma unroll 1
    for (int c = 0; c < 48; c++) {
        if (c + 1 < 48) {
            ld_chunk(c + 1, m0, n0, sb, tid);
            asm volatile("cp.async.wait_group 1;" ::: "memory");
        } else {
            asm volatile("cp.async.wait_group 0;" ::: "memory");
        }
        __syncthreads();
        uint32_t bufA = sb + (c & 1) * CH_BYTES;
        uint32_t bufB = bufA + 10240;
#pragma unroll
        for (int ks = 0; ks < 2; ks++) {
            uint32_t afr[4][4], bfr[2][4];
#pragma unroll
            for (int mt = 0; mt < 4; mt++)
                ldm4(afr[mt][0], afr[mt][1], afr[mt][2], afr[mt][3],
                     bufA + (wm * 64 + mt * 16 + a_row) * 80 + ks * 32 + a_kb);
#pragma unroll
            for (int p = 0; p < 2; p++)
                ldm4(bfr[p][0], bfr[p][1], bfr[p][2], bfr[p][3],
                     bufB + (wn * 32 + p * 16 + b_row) * 80 + ks * 32 + b_kb);
#pragma unroll
            for (int mt = 0; mt < 4; mt++)
#pragma unroll
                for (int nt = 0; nt < 4; nt++)
                    mma16816(acc[mt][nt], afr[mt], &bfr[nt >> 1][(nt & 1) * 2]);
        }
        __syncthreads();
    }

    // Epilogue: stage halves through SMEM; quantize i24 = rn(acc * -20 * 2048)
    float* stg = reinterpret_cast<float*>(smem);
#pragma unroll 1
    for (int h = 0; h < 2; h++) {
        if (wm == h) {
#pragma unroll
            for (int mt = 0; mt < 4; mt++)
#pragma unroll
                for (int nt = 0; nt < 4; nt++) {
                    int r0 = mt * 16 + (lane >> 2);
                    int cc = wn * 32 + nt * 8 + (lane & 3) * 2;
                    stg[r0 * 132 + cc]           = acc[mt][nt][0];
                    stg[r0 * 132 + cc + 1]       = acc[mt][nt][1];
                    stg[(r0 + 8) * 132 + cc]     = acc[mt][nt][2];
                    stg[(r0 + 8) * 132 + cc + 1] = acc[mt][nt][3];
                }
        }
        __syncthreads();
#pragma unroll
        for (int it = 0; it < 8; it++) {
            int idx = it * 256 + tid;
            int r = idx >> 5, c4 = idx & 31;
            float4 v = *reinterpret_cast<const float4*>(stg + r * 132 + c4 * 4);
            int i0 = __float2int_rn(v.x * -40960.f);
            int i1 = __float2int_rn(v.y * -40960.f);
            int i2 = __float2int_rn(v.z * -40960.f);
            int i3 = __float2int_rn(v.w * -40960.f);
            size_t off = (size_t)(m0 + h * 64 + r) * kNT + n0 + c4 * 4;
            short4 hs = make_short4((short)(i0 >> 8), (short)(i1 >> 8),
                                    (short)(i2 >> 8), (short)(i3 >> 8));
            uchar4 ls = make_uchar4((unsigned char)(i0 & 255), (unsigned char)(i1 & 255),
                                    (unsigned char)(i2 & 255), (unsigned char)(i3 & 255));
            *reinterpret_cast<short4*>(g_Mhi + off) = hs;
            *reinterpret_cast<uchar4*>(g_Mlo + off) = ls;
        }
        __syncthreads();
    }
}

// ---------------- logits / softmax / g init ----------------
__global__ void logits_kernel(const float* __restrict__ W2, const float* __restrict__ b2)
{
    int warp = threadIdx.x >> 5, lane = threadIdx.x & 31;
    int i = blockIdx.x * 8 + warp;
    const float* hr = g_h + (size_t)i * kH;
    float acc = 0.f;
#pragma unroll
    for (int d = lane; d < kH; d += 32) acc += hr[d] * W2[d];
#pragma unroll
    for (int off = 16; off; off >>= 1) acc += __shfl_down_sync(0xffffffffu, acc, off);
    if (lane == 0) g_logits[i] = acc + b2[0];
}

__global__ void softmax_log_kernel()
{
    __shared__ float red[1024];
    int t = threadIdx.x;
    float m = NEGINF;
    for (int i = t; i < kNA; i += 1024) m = fmaxf(m, g_logits[i]);
    red[t] = m; __syncthreads();
    for (int off = 512; off; off >>= 1) {
        if (t < off) red[t] = fmaxf(red[t], red[t + off]);
        __syncthreads();
    }
    float gm = red[0]; __syncthreads();
    float sum = 0.f;
    for (int i = t; i < kNA; i += 1024) sum += __expf(g_logits[i] - gm);
    red[t] = sum; __syncthreads();
    for (int off = 512; off; off >>= 1) {
        if (t < off) red[t] += red[t + off];
        __syncthreads();
    }
    float lse = gm + logf(red[0]);
    for (int i = t; i < kNA; i += 1024) g_logb[i] = g_logits[i] - lse;
}

__global__ void ginit_kernel()
{
    int warp = threadIdx.x >> 5, lane = threadIdx.x & 31;
    int j = blockIdx.x * 8 + warp;
    const float* kr = g_k + (size_t)j * kD;
    float acc = 0.f;
#pragma unroll
    for (int d = lane; d < kD; d += 32) { float v = kr[d]; acc += v * v; }
#pragma unroll
    for (int off = 16; off; off >>= 1) acc += __shfl_down_sync(0xffffffffu, acc, off);
    if (lane == 0) g_g[j] = INV_EPS * acc;
}

// ---------------- row LSE: 8 rows/block ----------------
__global__ void __launch_bounds__(256) row_lse_kernel()
{
    const int i0 = blockIdx.x * 8;
    const int t = threadIdx.x;
    float m[8], s[8];
#pragma unroll
    for (int r = 0; r < 8; r++) { m[r] = NEGINF; s[r] = 0.f; }
#pragma unroll 1
    for (int c = 0; c < 4; c++) {
        const int e0 = c * 2048 + t * 8;
        float gv[8];
        *reinterpret_cast<float4*>(gv)     = *reinterpret_cast<const float4*>(g_g + e0);
        *reinterpret_cast<float4*>(gv + 4) = *reinterpret_cast<const float4*>(g_g + e0 + 4);
#pragma unroll
        for (int r = 0; r < 8; r++) {
            size_t off = (size_t)(i0 + r) * kNT + e0;
            int4 w = *reinterpret_cast<const int4*>(g_Mhi + off);
            int2 b = *reinterpret_cast<const int2*>(g_Mlo + off);
            float x[8];
            dec8(w, b, gv, x);
            float lm = fmaxf(fmaxf(fmaxf(x[0], x[1]), fmaxf(x[2], x[3])),
                             fmaxf(fmaxf(x[4], x[5]), fmaxf(x[6], x[7])));
            float mn = fmaxf(m[r], lm);
            float a = __expf(x[0] - mn) + __expf(x[1] - mn) + __expf(x[2] - mn)
                    + __expf(x[3] - mn) + __expf(x[4] - mn) + __expf(x[5] - mn)
                    + __expf(x[6] - mn) + __expf(x[7] - mn);
            s[r] = s[r] * __expf(m[r] - mn) + a;
            m[r] = mn;
        }
    }
    __shared__ float sm[256], ss[256];
#pragma unroll 1
    for (int r = 0; r < 8; r++) {
        sm[t] = m[r]; ss[t] = s[r];
        __syncthreads();
        for (int off = 128; off; off >>= 1) {
            if (t < off) {
                float m2 = sm[t + off];
                float mn = fmaxf(sm[t], m2);
                ss[t] = ss[t] * __expf(sm[t] - mn) + ss[t + off] * __expf(m2 - mn);
                sm[t] = mn;
            }
            __syncthreads();
        }
        if (t == 0) g_f[i0 + r] = g_logb[i0 + r] - (sm[0] + logf(ss[0]));
        __syncthreads();
    }
}

// ---------------- column LSE (2 cols/thread) + fused combine ----------------
__global__ void __launch_bounds__(256) col_lse_kernel(float log_a)
{
    const int t = threadIdx.x;
    const int j0 = (blockIdx.x * 256 + t) * 2;
    const int seg = blockIdx.y, r0 = seg * 256;
    __shared__ float fs[256];
    fs[t] = g_f[r0 + t];
    __syncthreads();
    const short* hp = g_Mhi + (size_t)r0 * kNT + j0;
    const unsigned char* lp = g_Mlo + (size_t)r0 * kNT + j0;
    float mA = NEGINF, sA = 0.f, mB = NEGINF, sB = 0.f;
#pragma unroll 1
    for (int rb = 0; rb < 256; rb += 8) {
        float xa[8], xb[8];
#pragma unroll
        for (int r = 0; r < 8; r++) {
            int hw = *reinterpret_cast<const int*>(hp + (size_t)(rb + r) * kNT);
            uint32_t lw = *reinterpret_cast<const unsigned short*>(lp + (size_t)(rb + r) * kNT);
            int hA = (hw << 16) >> 16;
            int hB = hw >> 16;
            int lA = (int)(lw & 255), lB = (int)((lw >> 8) & 255);
            float fv = fs[rb + r];
            xa[r] = fmaf((float)(hA * 256 + lA), QSCALE, fv);
            xb[r] = fmaf((float)(hB * 256 + lB), QSCALE, fv);
        }
        float lmA = xa[0], lmB = xb[0];
#pragma unroll
        for (int r = 1; r < 8; r++) { lmA = fmaxf(lmA, xa[r]); lmB = fmaxf(lmB, xb[r]); }
        float mnA = fmaxf(mA, lmA), mnB = fmaxf(mB, lmB);
        float aA = 0.f, aB = 0.f;
#pragma unroll
        for (int r = 0; r < 8; r++) { aA += __expf(xa[r] - mnA); aB += __expf(xb[r] - mnB); }
        sA = sA * __expf(mA - mnA) + aA; mA = mnA;
        sB = sB * __expf(mB - mnB) + aB; mB = mnB;
    }
    *reinterpret_cast<float2*>(g_pm + (size_t)seg * kNT + j0) = make_float2(mA, mB);
    *reinterpret_cast<float2*>(g_ps + (size_t)seg * kNT + j0) = make_float2(sA, sB);

    // last-block-per-column-tile combines into g
    __threadfence();
    __syncthreads();                       // all partial writes done before count
    __shared__ int isLast;
    if (t == 0) {
        int d = atomicAdd(&g_cnt[blockIdx.x], 1);
        isLast = (d == 31);
    }
    __syncthreads();
    if (isLast) {
        __threadfence();
        float m2a = NEGINF, m2b = NEGINF;
#pragma unroll
        for (int sg = 0; sg < 32; sg++) {
            float2 v = *reinterpret_cast<const float2*>(g_pm + (size_t)sg * kNT + j0);
            m2a = fmaxf(m2a, v.x); m2b = fmaxf(m2b, v.y);
        }
        float s2a = 0.f, s2b = 0.f;
#pragma unroll
        for (int sg = 0; sg < 32; sg++) {
            float2 vm = *reinterpret_cast<const float2*>(g_pm + (size_t)sg * kNT + j0);
            float2 vs = *reinterpret_cast<const float2*>(g_ps + (size_t)sg * kNT + j0);
            s2a += vs.x * __expf(vm.x - m2a);
            s2b += vs.y * __expf(vm.y - m2b);
        }
        float2 go;
        go.x = log_a - (m2a + logf(s2a));
        go.y = log_a - (m2b + logf(s2b));
        *reinterpret_cast<float2*>(g_g + j0) = go;
        __syncthreads();
        if (t == 0) g_cnt[blockIdx.x] = 0;   // graph-replay-safe reset
    }
}

// ---------------- final T ----------------
__global__ void __launch_bounds__(256) final_T_kernel(float* __restrict__ out, float inv_total)
{
    int i = blockIdx.y;
    int e0 = (blockIdx.x * 256 + threadIdx.x) * 4;
    float fi = g_f[i];
    size_t off = (size_t)i * kNT + e0;
    short4 hw = *reinterpret_cast<const short4*>(g_Mhi + off);
    uint32_t lw = *reinterpret_cast<const uint32_t*>(g_Mlo + off);
    float4 gv = *reinterpret_cast<const float4*>(g_g + e0);
    int l0 = (int)(lw & 255), l1 = (int)((lw >> 8) & 255);
    int l2 = (int)((lw >> 16) & 255), l3 = (int)(lw >> 24);
    float4 o;
    o.x = __expf(fmaf((float)((int)hw.x * 256 + l0), QSCALE, fi + gv.x)) * inv_total;
    o.y = __expf(fmaf((float)((int)hw.y * 256 + l1), QSCALE, fi + gv.y)) * inv_total;
    o.z = __expf(fmaf((float)((int)hw.z * 256 + l2), QSCALE, fi + gv.z)) * inv_total;
    o.w = __expf(fmaf((float)((int)hw.w * 256 + l3), QSCALE, fi + gv.w)) * inv_total;
    *reinterpret_cast<float4*>(out + off) = o;
}

// ---------------- host ----------------
extern "C" void kernel_launch(void* const* d_in, const int* in_sizes, int n_in,
                              void* d_out, int out_size)
{
    const float* Aemb = (const float*)d_in[0];
    const float* Temb = (const float*)d_in[1];
    const float* Wq   = (const float*)d_in[2];
    const float* bq   = (const float*)d_in[3];
    const float* Wk   = (const float*)d_in[4];
    const float* bk   = (const float*)d_in[5];
    const float* W1   = (const float*)d_in[6];
    const float* b1   = (const float*)d_in[7];
    const float* W2   = (const float*)d_in[8];
    const float* b2   = (const float*)d_in[9];
    float* out = (float*)d_out;

    float *pq, *pk, *ph;
    __nv_bfloat16 *pqs, *pks;
    cudaGetSymbolAddress((void**)&pq, g_q);
    cudaGetSymbolAddress((void**)&pk, g_k);
    cudaGetSymbolAddress((void**)&ph, g_h);
    cudaGetSymbolAddress((void**)&pqs, g_qs);
    cudaGetSymbolAddress((void**)&pks, g_ks);

    gemm128_kernel<false><<<dim3(2, 64), 256>>>(Aemb, Wq, bq, pq, 256, 256);
    gemm128_kernel<false><<<dim3(2, 64), 256>>>(Temb, Wk, bk, pk, 256, 256);
    gemm128_kernel<true ><<<dim3(1, 64), 256>>>(Aemb, W1, b1, ph, 128, 256);
    logits_kernel<<<1024, 256>>>(W2, b2);
    softmax_log_kernel<<<1, 1024>>>();
    ginit_kernel<<<1024, 256>>>();

    split3_kernel<<<2048, 256>>>(pq, pqs, pqs + kNA * kD, pqs + 2 * kNA * kD);
    split3_kernel<<<2048, 256>>>(pk, pks, pks + kNT * kD, pks + 2 * kNT * kD);

    mgemm_kernel<<<dim3(64, 64), 256, MG_SMEM>>>();

    const float log_a = logf(1.0f / 8192.0f + 1e-20f);
    for (int it = 0; it < 50; it++) {
        row_lse_kernel<<<1024, 256>>>();
        col_lse_kernel<<<dim3(16, 32), 256>>>(log_a);
    }
    final_T_kernel<<<dim3(8, 8192), 256>>>(out, 1.0f / (1.0f + 1e-8f));
}

// round 10
// speedup vs baseline: 1.2102x; 1.2102x over previous
#include <cuda_runtime.h>
#include <cuda_bf16.h>
#include <math.h>
#include <stdint.h>

#define kNA 8192
#define kNT 8192
#define kD  256
#define kH  128
#define INV_EPS 10.0f
#define QSCALE 4.8828125e-4f   /* 2^-11 */
#define LOG2E 1.4426950408889634f
#define NEGINF -3.402823466e38f

__device__ float g_q[kNA * kD];
__device__ float g_k[kNT * kD];
__device__ float g_h[kNA * kH];
__device__ float g_logits[kNA];
__device__ float g_logb[kNA];
__device__ float g_f[kNA];
__device__ float g_g[kNT];
__device__ short g_Mhi[67108864];
__device__ unsigned char g_Mlo[67108864];
__device__ float g_pm[32 * kNT];
__device__ float g_ps[32 * kNT];
__device__ int   g_cnt[16];
__device__ __nv_bfloat16 g_qs[3][kNA * kD];
__device__ __nv_bfloat16 g_ks[3][kNT * kD];

// ---------------- helpers ----------------
__device__ __forceinline__ uint32_t smem_u32(const void* p) {
    uint32_t a;
    asm("{ .reg .u64 t; cvta.to.shared.u64 t, %1; cvt.u32.u64 %0, t; }" : "=r"(a) : "l"(p));
    return a;
}
__device__ __forceinline__ void cp16(uint32_t s, const void* g) {
    asm volatile("cp.async.cg.shared.global [%0], [%1], 16;" :: "r"(s), "l"(g));
}
__device__ __forceinline__ void ldm4(uint32_t& r0, uint32_t& r1, uint32_t& r2,
                                     uint32_t& r3, uint32_t a) {
    asm volatile("ldmatrix.sync.aligned.m8n8.x4.shared.b16 {%0,%1,%2,%3}, [%4];"
                 : "=r"(r0), "=r"(r1), "=r"(r2), "=r"(r3) : "r"(a));
}
__device__ __forceinline__ void mma16816(float* c, const uint32_t* a, const uint32_t* b) {
    asm volatile("mma.sync.aligned.m16n8k16.row.col.f32.bf16.bf16.f32 "
                 "{%0,%1,%2,%3}, {%4,%5,%6,%7}, {%8,%9}, {%0,%1,%2,%3};"
                 : "+f"(c[0]), "+f"(c[1]), "+f"(c[2]), "+f"(c[3])
                 : "r"(a[0]), "r"(a[1]), "r"(a[2]), "r"(a[3]), "r"(b[0]), "r"(b[1]));
}
__device__ __forceinline__ float ex2(float x) {
    float r;
    asm("ex2.approx.f32 %0, %1;" : "=f"(r) : "f"(x));
    return r;
}
// exp(d) with d = x - mn computed FIRST (numerically safe)
__device__ __forceinline__ float expd(float d) { return ex2(d * LOG2E); }

// magic decode (exact): i24*QSCALE from bit patterns
__device__ __forceinline__ float dec_hi(uint32_t bits) {
    return fmaf(__uint_as_float(bits), 0.125f, -1052672.0f);       // = hi/8
}
__device__ __forceinline__ float dec_lo(uint32_t bits) {
    return fmaf(__uint_as_float(bits), QSCALE, -4096.0f);          // = lo/2048
}
__device__ __forceinline__ void dec8(int4 w, int2 b, const float* gv, float* x) {
    uint32_t wp[4] = {(uint32_t)w.x, (uint32_t)w.y, (uint32_t)w.z, (uint32_t)w.w};
    uint32_t lb[2] = {(uint32_t)b.x, (uint32_t)b.y};
#pragma unroll
    for (int p = 0; p < 4; p++) {
        uint32_t hA = (wp[p] & 0xFFFFu) ^ 0x4B008000u;
        uint32_t hB = (wp[p] >> 16) ^ 0x4B008000u;
        uint32_t lA = __byte_perm(lb[p >> 1], 0x4B000000u, 0x7440u + ((p & 1) * 2));
        uint32_t lB = __byte_perm(lb[p >> 1], 0x4B000000u, 0x7441u + ((p & 1) * 2));
        x[p * 2]     = dec_hi(hA) + (dec_lo(lA) + gv[p * 2]);
        x[p * 2 + 1] = dec_hi(hB) + (dec_lo(lB) + gv[p * 2 + 1]);
    }
}

// ---------------- small SIMT GEMM (q,k,h) ----------------
template<bool RELU>
__global__ void __launch_bounds__(256, 2) gemm128_kernel(
    const float* __restrict__ A, const float* __restrict__ B,
    const float* __restrict__ bias, float* __restrict__ C, int N, int K)
{
    __shared__ float As[16][130];
    __shared__ float Bs[16][130];
    const int tid = threadIdx.x, tx = tid & 15, ty = tid >> 4;
    const int m0 = blockIdx.y * 128, n0 = blockIdx.x * 128;
    const int lr = tid >> 2, lk = (tid & 3) << 2;
    float acc[8][8];
#pragma unroll
    for (int i = 0; i < 8; i++)
#pragma unroll
        for (int j = 0; j < 8; j++) acc[i][j] = 0.f;
    for (int k0 = 0; k0 < K; k0 += 16) {
#pragma unroll
        for (int h = 0; h < 2; h++) {
            int row = lr + h * 64;
            float4 v = *reinterpret_cast<const float4*>(A + (size_t)(m0 + row) * K + k0 + lk);
            As[lk + 0][row] = v.x; As[lk + 1][row] = v.y;
            As[lk + 2][row] = v.z; As[lk + 3][row] = v.w;
        }
        {
            int kk = tid >> 4, nx = (tid & 15) << 2;
#pragma unroll
            for (int h = 0; h < 2; h++) {
                int n = nx + h * 64;
                float4 v = *reinterpret_cast<const float4*>(B + (size_t)(k0 + kk) * N + n0 + n);
                Bs[kk][n + 0] = v.x; Bs[kk][n + 1] = v.y;
                Bs[kk][n + 2] = v.z; Bs[kk][n + 3] = v.w;
            }
        }
        __syncthreads();
#pragma unroll
        for (int kk = 0; kk < 16; kk++) {
            float a[8], b[8];
#pragma unroll
            for (int e = 0; e < 4; e++) {
                a[e] = As[kk][ty * 4 + e];     a[e + 4] = As[kk][ty * 4 + 64 + e];
                b[e] = Bs[kk][tx * 4 + e];     b[e + 4] = Bs[kk][tx * 4 + 64 + e];
            }
#pragma unroll
            for (int i = 0; i < 8; i++)
#pragma unroll
                for (int j = 0; j < 8; j++) acc[i][j] += a[i] * b[j];
        }
        __syncthreads();
    }
#pragma unroll
    for (int i = 0; i < 8; i++) {
        int row = m0 + ty * 4 + (i < 4 ? i : i - 4 + 64);
#pragma unroll
        for (int jh = 0; jh < 2; jh++) {
            int col = n0 + tx * 4 + jh * 64;
            float4 v;
            v.x = acc[i][jh * 4 + 0] + bias[col + 0];
            v.y = acc[i][jh * 4 + 1] + bias[col + 1];
            v.z = acc[i][jh * 4 + 2] + bias[col + 2];
            v.w = acc[i][jh * 4 + 3] + bias[col + 3];
            if (RELU) {
                v.x = fmaxf(v.x, 0.f); v.y = fmaxf(v.y, 0.f);
                v.z = fmaxf(v.z, 0.f); v.w = fmaxf(v.w, 0.f);
            }
            *reinterpret_cast<float4*>(C + (size_t)row * N + col) = v;
        }
    }
}

// ---------------- bf16x3 split ----------------
__global__ void __launch_bounds__(256) split3_kernel(
    const float* __restrict__ x, __nv_bfloat16* __restrict__ h0,
    __nv_bfloat16* __restrict__ l0, __nv_bfloat16* __restrict__ l1)
{
    int i = (blockIdx.x * 256 + threadIdx.x) * 4;
    float4 v = *reinterpret_cast<const float4*>(x + i);
    float vs[4] = {v.x, v.y, v.z, v.w};
    __nv_bfloat16 hh[4], ll[4], mm[4];
#pragma unroll
    for (int c = 0; c < 4; c++) {
        __nv_bfloat16 h = __float2bfloat16(vs[c]);
        float r = vs[c] - __bfloat162float(h);
        __nv_bfloat16 l = __float2bfloat16(r);
        hh[c] = h; ll[c] = l; mm[c] = __float2bfloat16(r - __bfloat162float(l));
    }
    *reinterpret_cast<__nv_bfloat162*>(h0 + i)     = __nv_bfloat162{hh[0], hh[1]};
    *reinterpret_cast<__nv_bfloat162*>(h0 + i + 2) = __nv_bfloat162{hh[2], hh[3]};
    *reinterpret_cast<__nv_bfloat162*>(l0 + i)     = __nv_bfloat162{ll[0], ll[1]};
    *reinterpret_cast<__nv_bfloat162*>(l0 + i + 2) = __nv_bfloat162{ll[2], ll[3]};
    *reinterpret_cast<__nv_bfloat162*>(l1 + i)     = __nv_bfloat162{mm[0], mm[1]};
    *reinterpret_cast<__nv_bfloat162*>(l1 + i + 2) = __nv_bfloat162{mm[2], mm[3]};
}

// ---------------- mma.sync GEMM -> quantized M (24-bit) ----------------
#define CH_BYTES 20480
#define MG_SMEM  40960

__device__ __forceinline__ void ld_chunk(int c, int m0, int n0, uint32_t sb, int tid)
{
    int term = c >> 3, kc = (c & 7) * 32;
    int at = (0x850 >> (term * 2)) & 3;
    int bt = (0x244 >> (term * 2)) & 3;
    const __nv_bfloat16* A = &g_qs[at][0] + (size_t)m0 * kD + kc;
    const __nv_bfloat16* B = &g_ks[bt][0] + (size_t)n0 * kD + kc;
    uint32_t base = sb + (c & 1) * CH_BYTES;
#pragma unroll
    for (int i = 0; i < 4; i++) {
        int idx = i * 256 + tid;
        int mat = idx >> 9, j = idx & 511;
        int row = j >> 2, seg = j & 3;
        const __nv_bfloat16* src = (mat ? B : A) + (size_t)row * kD + seg * 8;
        cp16(base + mat * 10240 + row * 80 + seg * 16, src);
    }
    asm volatile("cp.async.commit_group;" ::: "memory");
}

__global__ void __launch_bounds__(256) mgemm_kernel()
{
    extern __shared__ char smem[];
    uint32_t sb = smem_u32(smem);
    const int tid = threadIdx.x, wid = tid >> 5, lane = tid & 31;
    const int wm = wid & 1, wn = wid >> 1;
    const int m0 = blockIdx.y * 128, n0 = blockIdx.x * 128;

    float acc[4][4][4];
#pragma unroll
    for (int i = 0; i < 4; i++)
#pragma unroll
        for (int j = 0; j < 4; j++)
#pragma unroll
            for (int e = 0; e < 4; e++) acc[i][j][e] = 0.f;

    const int a_row = lane & 15;
    const int a_kb  = (lane >> 4) * 16;
    const int b_row = (lane & 7) + ((lane >> 4) << 3);
    const int b_kb  = ((lane >> 3) & 1) * 16;

    ld_chunk(0, m0, n0, sb, tid);
#pragma unroll 1
    for (int c = 0; c < 48; c++) {
        if (c + 1 < 48) {
            ld_chunk(c + 1, m0, n0, sb, tid);
            asm volatile("cp.async.wait_group 1;" ::: "memory");
        } else {
            asm volatile("cp.async.wait_group 0;" ::: "memory");
        }
        __syncthreads();
        uint32_t bufA = sb + (c & 1) * CH_BYTES;
        uint32_t bufB = bufA + 10240;
#pragma unroll
        for (int ks = 0; ks < 2; ks++) {
            uint32_t afr[4][4], bfr[2][4];
#pragma unroll
            for (int mt = 0; mt < 4; mt++)
                ldm4(afr[mt][0], afr[mt][1], afr[mt][2], afr[mt][3],
                     bufA + (wm * 64 + mt * 16 + a_row) * 80 + ks * 32 + a_kb);
#pragma unroll
            for (int p = 0; p < 2; p++)
                ldm4(bfr[p][0], bfr[p][1], bfr[p][2], bfr[p][3],
                     bufB + (wn * 32 + p * 16 + b_row) * 80 + ks * 32 + b_kb);
#pragma unroll
            for (int mt = 0; mt < 4; mt++)
#pragma unroll
                for (int nt = 0; nt < 4; nt++)
                    mma16816(acc[mt][nt], afr[mt], &bfr[nt >> 1][(nt & 1) * 2]);
        }
        __syncthreads();
    }

    float* stg = reinterpret_cast<float*>(smem);
#pragma unroll 1
    for (int h = 0; h < 2; h++) {
        if (wm == h) {
#pragma unroll
            for (int mt = 0; mt < 4; mt++)
#pragma unroll
                for (int nt = 0; nt < 4; nt++) {
                    int r0 = mt * 16 + (lane >> 2);
                    int cc = wn * 32 + nt * 8 + (lane & 3) * 2;
                    stg[r0 * 132 + cc]           = acc[mt][nt][0];
                    stg[r0 * 132 + cc + 1]       = acc[mt][nt][1];
                    stg[(r0 + 8) * 132 + cc]     = acc[mt][nt][2];
                    stg[(r0 + 8) * 132 + cc + 1] = acc[mt][nt][3];
                }
        }
        __syncthreads();
#pragma unroll
        for (int it = 0; it < 8; it++) {
            int idx = it * 256 + tid;
            int r = idx >> 5, c4 = idx & 31;
            float4 v = *reinterpret_cast<const float4*>(stg + r * 132 + c4 * 4);
            int i0 = __float2int_rn(v.x * -40960.f);
            int i1 = __float2int_rn(v.y * -40960.f);
            int i2 = __float2int_rn(v.z * -40960.f);
            int i3 = __float2int_rn(v.w * -40960.f);
            size_t off = (size_t)(m0 + h * 64 + r) * kNT + n0 + c4 * 4;
            short4 hs = make_short4((short)(i0 >> 8), (short)(i1 >> 8),
                                    (short)(i2 >> 8), (short)(i3 >> 8));
            uchar4 ls = make_uchar4((unsigned char)(i0 & 255), (unsigned char)(i1 & 255),
                                    (unsigned char)(i2 & 255), (unsigned char)(i3 & 255));
            *reinterpret_cast<short4*>(g_Mhi + off) = hs;
            *reinterpret_cast<uchar4*>(g_Mlo + off) = ls;
        }
        __syncthreads();
    }
}

// ---------------- logits / softmax / g init ----------------
__global__ void logits_kernel(const float* __restrict__ W2, const float* __restrict__ b2)
{
    int warp = threadIdx.x >> 5, lane = threadIdx.x & 31;
    int i = blockIdx.x * 8 + warp;
    const float* hr = g_h + (size_t)i * kH;
    float acc = 0.f;
#pragma unroll
    for (int d = lane; d < kH; d += 32) acc += hr[d] * W2[d];
#pragma unroll
    for (int off = 16; off; off >>= 1) acc += __shfl_down_sync(0xffffffffu, acc, off);
    if (lane == 0) g_logits[i] = acc + b2[0];
}

__global__ void softmax_log_kernel()
{
    __shared__ float red[1024];
    int t = threadIdx.x;
    float m = NEGINF;
    for (int i = t; i < kNA; i += 1024) m = fmaxf(m, g_logits[i]);
    red[t] = m; __syncthreads();
    for (int off = 512; off; off >>= 1) {
        if (t < off) red[t] = fmaxf(red[t], red[t + off]);
        __syncthreads();
    }
    float gm = red[0]; __syncthreads();
    float sum = 0.f;
    for (int i = t; i < kNA; i += 1024) sum += __expf(g_logits[i] - gm);
    red[t] = sum; __syncthreads();
    for (int off = 512; off; off >>= 1) {
        if (t < off) red[t] += red[t + off];
        __syncthreads();
    }
    float lse = gm + logf(red[0]);
    for (int i = t; i < kNA; i += 1024) g_logb[i] = g_logits[i] - lse;
}

__global__ void ginit_kernel()
{
    int warp = threadIdx.x >> 5, lane = threadIdx.x & 31;
    int j = blockIdx.x * 8 + warp;
    const float* kr = g_k + (size_t)j * kD;
    float acc = 0.f;
#pragma unroll
    for (int d = lane; d < kD; d += 32) { float v = kr[d]; acc += v * v; }
#pragma unroll
    for (int off = 16; off; off >>= 1) acc += __shfl_down_sync(0xffffffffu, acc, off);
    if (lane == 0) g_g[j] = INV_EPS * acc;
}

// ---------------- row LSE: 4 rows/block, difference-first exp ----------
__global__ void __launch_bounds__(256) row_lse_kernel()
{
    const int i0 = blockIdx.x * 4;
    const int t = threadIdx.x;
    float m[4], s[4];
#pragma unroll
    for (int r = 0; r < 4; r++) { m[r] = NEGINF; s[r] = 0.f; }
#pragma unroll 1
    for (int c = 0; c < 4; c++) {
        const int e0 = c * 2048 + t * 8;
        float gv[8];
        *reinterpret_cast<float4*>(gv)     = *reinterpret_cast<const float4*>(g_g + e0);
        *reinterpret_cast<float4*>(gv + 4) = *reinterpret_cast<const float4*>(g_g + e0 + 4);
#pragma unroll
        for (int r = 0; r < 4; r++) {
            size_t off = (size_t)(i0 + r) * kNT + e0;
            int4 w = *reinterpret_cast<const int4*>(g_Mhi + off);
            int2 b = *reinterpret_cast<const int2*>(g_Mlo + off);
            float x[8];
            dec8(w, b, gv, x);
            float lm = fmaxf(fmaxf(fmaxf(x[0], x[1]), fmaxf(x[2], x[3])),
                             fmaxf(fmaxf(x[4], x[5]), fmaxf(x[6], x[7])));
            float mn = fmaxf(m[r], lm);
            float a = expd(x[0] - mn) + expd(x[1] - mn) + expd(x[2] - mn)
                    + expd(x[3] - mn) + expd(x[4] - mn) + expd(x[5] - mn)
                    + expd(x[6] - mn) + expd(x[7] - mn);
            s[r] = s[r] * expd(m[r] - mn) + a;
            m[r] = mn;
        }
    }
    __shared__ float sm[256], ss[256];
#pragma unroll 1
    for (int r = 0; r < 4; r++) {
        sm[t] = m[r]; ss[t] = s[r];
        __syncthreads();
        for (int off = 128; off; off >>= 1) {
            if (t < off) {
                float m2 = sm[t + off];
                float mn = fmaxf(sm[t], m2);
                ss[t] = ss[t] * expd(sm[t] - mn) + ss[t + off] * expd(m2 - mn);
                sm[t] = mn;
            }
            __syncthreads();
        }
        if (t == 0) g_f[i0 + r] = g_logb[i0 + r] - (sm[0] + logf(ss[0]));
        __syncthreads();
    }
}

// ---------------- column LSE (2 cols/thread) + fused combine ----------------
__global__ void __launch_bounds__(256) col_lse_kernel(float log_a)
{
    const int t = threadIdx.x;
    const int j0 = (blockIdx.x * 256 + t) * 2;
    const int seg = blockIdx.y, r0 = seg * 256;
    __shared__ float fs[256];
    fs[t] = g_f[r0 + t];
    __syncthreads();
    const short* hp = g_Mhi + (size_t)r0 * kNT + j0;
    const unsigned char* lp = g_Mlo + (size_t)r0 * kNT + j0;
    float mA = NEGINF, sA = 0.f, mB = NEGINF, sB = 0.f;
#pragma unroll 1
    for (int rb = 0; rb < 256; rb += 8) {
        float xa[8], xb[8];
#pragma unroll
        for (int r = 0; r < 8; r++) {
            uint32_t hw = *reinterpret_cast<const unsigned int*>(hp + (size_t)(rb + r) * kNT);
            uint32_t lw = *reinterpret_cast<const unsigned short*>(lp + (size_t)(rb + r) * kNT);
            uint32_t hA = (hw & 0xFFFFu) ^ 0x4B008000u;
            uint32_t hB = (hw >> 16) ^ 0x4B008000u;
            uint32_t lA = __byte_perm(lw, 0x4B000000u, 0x7440u);
            uint32_t lB = __byte_perm(lw, 0x4B000000u, 0x7441u);
            float fv = fs[rb + r];
            xa[r] = dec_hi(hA) + (dec_lo(lA) + fv);
            xb[r] = dec_hi(hB) + (dec_lo(lB) + fv);
        }
        float lmA = xa[0], lmB = xb[0];
#pragma unroll
        for (int r = 1; r < 8; r++) { lmA = fmaxf(lmA, xa[r]); lmB = fmaxf(lmB, xb[r]); }
        float mnA = fmaxf(mA, lmA), mnB = fmaxf(mB, lmB);
        float aA = 0.f, aB = 0.f;
#pragma unroll
        for (int r = 0; r < 8; r++) {
            aA += expd(xa[r] - mnA);
            aB += expd(xb[r] - mnB);
        }
        sA = sA * expd(mA - mnA) + aA; mA = mnA;
        sB = sB * expd(mB - mnB) + aB; mB = mnB;
    }
    *reinterpret_cast<float2*>(g_pm + (size_t)seg * kNT + j0) = make_float2(mA, mB);
    *reinterpret_cast<float2*>(g_ps + (size_t)seg * kNT + j0) = make_float2(sA, sB);

    __threadfence();
    __syncthreads();
    __shared__ int isLast;
    if (t == 0) {
        int d = atomicAdd(&g_cnt[blockIdx.x], 1);
        isLast = (d == 31);
    }
    __syncthreads();
    if (isLast) {
        __threadfence();
        float m2a = NEGINF, m2b = NEGINF;
#pragma unroll
        for (int sg = 0; sg < 32; sg++) {
            float2 v = *reinterpret_cast<const float2*>(g_pm + (size_t)sg * kNT + j0);
            m2a = fmaxf(m2a, v.x); m2b = fmaxf(m2b, v.y);
        }
        float s2a = 0.f, s2b = 0.f;
#pragma unroll
        for (int sg = 0; sg < 32; sg++) {
            float2 vm = *reinterpret_cast<const float2*>(g_pm + (size_t)sg * kNT + j0);
            float2 vs = *reinterpret_cast<const float2*>(g_ps + (size_t)sg * kNT + j0);
            s2a += vs.x * __expf(vm.x - m2a);
            s2b += vs.y * __expf(vm.y - m2b);
        }
        float2 go;
        go.x = log_a - (m2a + logf(s2a));
        go.y = log_a - (m2b + logf(s2b));
        *reinterpret_cast<float2*>(g_g + j0) = go;
        __syncthreads();
        if (t == 0) g_cnt[blockIdx.x] = 0;
    }
}

// ---------------- final T ----------------
__global__ void __launch_bounds__(256) final_T_kernel(float* __restrict__ out, float inv_total)
{
    int i = blockIdx.y;
    int e0 = (blockIdx.x * 256 + threadIdx.x) * 8;
    float fi = g_f[i];
    size_t off = (size_t)i * kNT + e0;
    int4 w = *reinterpret_cast<const int4*>(g_Mhi + off);
    int2 b = *reinterpret_cast<const int2*>(g_Mlo + off);
    float gv[8];
    *reinterpret_cast<float4*>(gv)     = *reinterpret_cast<const float4*>(g_g + e0);
    *reinterpret_cast<float4*>(gv + 4) = *reinterpret_cast<const float4*>(g_g + e0 + 4);
#pragma unroll
    for (int k2 = 0; k2 < 8; k2++) gv[k2] += fi;
    float x[8];
    dec8(w, b, gv, x);
    float o[8];
#pragma unroll
    for (int k2 = 0; k2 < 8; k2++) o[k2] = ex2(x[k2] * LOG2E) * inv_total;
    *reinterpret_cast<float4*>(out + off)     = *reinterpret_cast<float4*>(o);
    *reinterpret_cast<float4*>(out + off + 4) = *reinterpret_cast<float4*>(o + 4);
}

// ---------------- host ----------------
extern "C" void kernel_launch(void* const* d_in, const int* in_sizes, int n_in,
                              void* d_out, int out_size)
{
    const float* Aemb = (const float*)d_in[0];
    const float* Temb = (const float*)d_in[1];
    const float* Wq   = (const float*)d_in[2];
    const float* bq   = (const float*)d_in[3];
    const float* Wk   = (const float*)d_in[4];
    const float* bk   = (const float*)d_in[5];
    const float* W1   = (const float*)d_in[6];
    const float* b1   = (const float*)d_in[7];
    const float* W2   = (const float*)d_in[8];
    const float* b2   = (const float*)d_in[9];
    float* out = (float*)d_out;

    float *pq, *pk, *ph;
    __nv_bfloat16 *pqs, *pks;
    cudaGetSymbolAddress((void**)&pq, g_q);
    cudaGetSymbolAddress((void**)&pk, g_k);
    cudaGetSymbolAddress((void**)&ph, g_h);
    cudaGetSymbolAddress((void**)&pqs, g_qs);
    cudaGetSymbolAddress((void**)&pks, g_ks);

    gemm128_kernel<false><<<dim3(2, 64), 256>>>(Aemb, Wq, bq, pq, 256, 256);
    gemm128_kernel<false><<<dim3(2, 64), 256>>>(Temb, Wk, bk, pk, 256, 256);
    gemm128_kernel<true ><<<dim3(1, 64), 256>>>(Aemb, W1, b1, ph, 128, 256);
    logits_kernel<<<1024, 256>>>(W2, b2);
    softmax_log_kernel<<<1, 1024>>>();
    ginit_kernel<<<1024, 256>>>();

    split3_kernel<<<2048, 256>>>(pq, pqs, pqs + kNA * kD, pqs + 2 * kNA * kD);
    split3_kernel<<<2048, 256>>>(pk, pks, pks + kNT * kD, pks + 2 * kNT * kD);

    mgemm_kernel<<<dim3(64, 64), 256, MG_SMEM>>>();

    const float log_a = logf(1.0f / 8192.0f + 1e-20f);
    for (int it = 0; it < 50; it++) {
        row_lse_kernel<<<2048, 256>>>();
        col_lse_kernel<<<dim3(16, 32), 256>>>(log_a);
    }
    final_T_kernel<<<dim3(4, 8192), 256>>>(out, 1.0f / (1.0f + 1e-8f));
}

// round 11
// speedup vs baseline: 1.3615x; 1.1250x over previous
#include <cuda_runtime.h>
#include <cuda_bf16.h>
#include <math.h>
#include <stdint.h>

#define kNA 8192
#define kNT 8192
#define kD  256
#define kH  128
#define INV_EPS 10.0f
#define NEGINF -3.402823466e38f

__device__ float g_q[kNA * kD];
__device__ float g_k[kNT * kD];
__device__ float g_h[kNA * kH];
__device__ float g_logits[kNA];
__device__ float g_logb[kNA];
__device__ float g_f[kNA];
__device__ float g_g[kNT];
__device__ float g_M[67108864];          // fp32 M (reverted: fastest proven sweep)
__device__ float g_pm[32 * kNT];
__device__ float g_ps[32 * kNT];
__device__ int   g_cnt[16];
__device__ __nv_bfloat16 g_qs[3][kNA * kD];
__device__ __nv_bfloat16 g_ks[3][kNT * kD];

// ---------------- helpers ----------------
__device__ __forceinline__ uint32_t smem_u32(const void* p) {
    uint32_t a;
    asm("{ .reg .u64 t; cvta.to.shared.u64 t, %1; cvt.u32.u64 %0, t; }" : "=r"(a) : "l"(p));
    return a;
}
__device__ __forceinline__ void cp16(uint32_t s, const void* g) {
    asm volatile("cp.async.cg.shared.global [%0], [%1], 16;" :: "r"(s), "l"(g));
}
__device__ __forceinline__ void ldm4(uint32_t& r0, uint32_t& r1, uint32_t& r2,
                                     uint32_t& r3, uint32_t a) {
    asm volatile("ldmatrix.sync.aligned.m8n8.x4.shared.b16 {%0,%1,%2,%3}, [%4];"
                 : "=r"(r0), "=r"(r1), "=r"(r2), "=r"(r3) : "r"(a));
}
__device__ __forceinline__ void mma16816(float* c, const uint32_t* a, const uint32_t* b) {
    asm volatile("mma.sync.aligned.m16n8k16.row.col.f32.bf16.bf16.f32 "
                 "{%0,%1,%2,%3}, {%4,%5,%6,%7}, {%8,%9}, {%0,%1,%2,%3};"
                 : "+f"(c[0]), "+f"(c[1]), "+f"(c[2]), "+f"(c[3])
                 : "r"(a[0]), "r"(a[1]), "r"(a[2]), "r"(a[3]), "r"(b[0]), "r"(b[1]));
}

// ---------------- small SIMT GEMM (q,k,h) ----------------
template<bool RELU>
__global__ void __launch_bounds__(256, 2) gemm128_kernel(
    const float* __restrict__ A, const float* __restrict__ B,
    const float* __restrict__ bias, float* __restrict__ C, int N, int K)
{
    __shared__ float As[16][130];
    __shared__ float Bs[16][130];
    const int tid = threadIdx.x, tx = tid & 15, ty = tid >> 4;
    const int m0 = blockIdx.y * 128, n0 = blockIdx.x * 128;
    const int lr = tid >> 2, lk = (tid & 3) << 2;
    float acc[8][8];
#pragma unroll
    for (int i = 0; i < 8; i++)
#pragma unroll
        for (int j = 0; j < 8; j++) acc[i][j] = 0.f;
    for (int k0 = 0; k0 < K; k0 += 16) {
#pragma unroll
        for (int h = 0; h < 2; h++) {
            int row = lr + h * 64;
            float4 v = *reinterpret_cast<const float4*>(A + (size_t)(m0 + row) * K + k0 + lk);
            As[lk + 0][row] = v.x; As[lk + 1][row] = v.y;
            As[lk + 2][row] = v.z; As[lk + 3][row] = v.w;
        }
        {
            int kk = tid >> 4, nx = (tid & 15) << 2;
#pragma unroll
            for (int h = 0; h < 2; h++) {
                int n = nx + h * 64;
                float4 v = *reinterpret_cast<const float4*>(B + (size_t)(k0 + kk) * N + n0 + n);
                Bs[kk][n + 0] = v.x; Bs[kk][n + 1] = v.y;
                Bs[kk][n + 2] = v.z; Bs[kk][n + 3] = v.w;
            }
        }
        __syncthreads();
#pragma unroll
        for (int kk = 0; kk < 16; kk++) {
            float a[8], b[8];
#pragma unroll
            for (int e = 0; e < 4; e++) {
                a[e] = As[kk][ty * 4 + e];     a[e + 4] = As[kk][ty * 4 + 64 + e];
                b[e] = Bs[kk][tx * 4 + e];     b[e + 4] = Bs[kk][tx * 4 + 64 + e];
            }
#pragma unroll
            for (int i = 0; i < 8; i++)
#pragma unroll
                for (int j = 0; j < 8; j++) acc[i][j] += a[i] * b[j];
        }
        __syncthreads();
    }
#pragma unroll
    for (int i = 0; i < 8; i++) {
        int row = m0 + ty * 4 + (i < 4 ? i : i - 4 + 64);
#pragma unroll
        for (int jh = 0; jh < 2; jh++) {
            int col = n0 + tx * 4 + jh * 64;
            float4 v;
            v.x = acc[i][jh * 4 + 0] + bias[col + 0];
            v.y = acc[i][jh * 4 + 1] + bias[col + 1];
            v.z = acc[i][jh * 4 + 2] + bias[col + 2];
            v.w = acc[i][jh * 4 + 3] + bias[col + 3];
            if (RELU) {
                v.x = fmaxf(v.x, 0.f); v.y = fmaxf(v.y, 0.f);
                v.z = fmaxf(v.z, 0.f); v.w = fmaxf(v.w, 0.f);
            }
            *reinterpret_cast<float4*>(C + (size_t)row * N + col) = v;
        }
    }
}

// ---------------- bf16x3 split ----------------
__global__ void __launch_bounds__(256) split3_kernel(
    const float* __restrict__ x, __nv_bfloat16* __restrict__ h0,
    __nv_bfloat16* __restrict__ l0, __nv_bfloat16* __restrict__ l1)
{
    int i = (blockIdx.x * 256 + threadIdx.x) * 4;
    float4 v = *reinterpret_cast<const float4*>(x + i);
    float vs[4] = {v.x, v.y, v.z, v.w};
    __nv_bfloat16 hh[4], ll[4], mm[4];
#pragma unroll
    for (int c = 0; c < 4; c++) {
        __nv_bfloat16 h = __float2bfloat16(vs[c]);
        float r = vs[c] - __bfloat162float(h);
        __nv_bfloat16 l = __float2bfloat16(r);
        hh[c] = h; ll[c] = l; mm[c] = __float2bfloat16(r - __bfloat162float(l));
    }
    *reinterpret_cast<__nv_bfloat162*>(h0 + i)     = __nv_bfloat162{hh[0], hh[1]};
    *reinterpret_cast<__nv_bfloat162*>(h0 + i + 2) = __nv_bfloat162{hh[2], hh[3]};
    *reinterpret_cast<__nv_bfloat162*>(l0 + i)     = __nv_bfloat162{ll[0], ll[1]};
    *reinterpret_cast<__nv_bfloat162*>(l0 + i + 2) = __nv_bfloat162{ll[2], ll[3]};
    *reinterpret_cast<__nv_bfloat162*>(l1 + i)     = __nv_bfloat162{mm[0], mm[1]};
    *reinterpret_cast<__nv_bfloat162*>(l1 + i + 2) = __nv_bfloat162{mm[2], mm[3]};
}

// ---------------- mma.sync GEMM: M = -20 q k^T (bf16x3, 6 terms) -----------
#define CH_BYTES 20480
#define MG_SMEM  40960

__device__ __forceinline__ void ld_chunk(int c, int m0, int n0, uint32_t sb, int tid)
{
    int term = c >> 3, kc = (c & 7) * 32;
    int at = (0x850 >> (term * 2)) & 3;   // {0,0,1,1,0,2}
    int bt = (0x244 >> (term * 2)) & 3;   // {0,1,0,1,2,0}
    const __nv_bfloat16* A = &g_qs[at][0] + (size_t)m0 * kD + kc;
    const __nv_bfloat16* B = &g_ks[bt][0] + (size_t)n0 * kD + kc;
    uint32_t base = sb + (c & 1) * CH_BYTES;
#pragma unroll
    for (int i = 0; i < 4; i++) {
        int idx = i * 256 + tid;
        int mat = idx >> 9, j = idx & 511;
        int row = j >> 2, seg = j & 3;
        const __nv_bfloat16* src = (mat ? B : A) + (size_t)row * kD + seg * 8;
        cp16(base + mat * 10240 + row * 80 + seg * 16, src);
    }
    asm volatile("cp.async.commit_group;" ::: "memory");
}

__global__ void __launch_bounds__(256) mgemm_kernel()
{
    extern __shared__ char smem[];
    uint32_t sb = smem_u32(smem);
    const int tid = threadIdx.x, wid = tid >> 5, lane = tid & 31;
    const int wm = wid & 1, wn = wid >> 1;
    const int m0 = blockIdx.y * 128, n0 = blockIdx.x * 128;

    float acc[4][4][4];
#pragma unroll
    for (int i = 0; i < 4; i++)
#pragma unroll
        for (int j = 0; j < 4; j++)
#pragma unroll
            for (int e = 0; e < 4; e++) acc[i][j][e] = 0.f;

    const int a_row = lane & 15;
    const int a_kb  = (lane >> 4) * 16;
    const int b_row = (lane & 7) + ((lane >> 4) << 3);
    const int b_kb  = ((lane >> 3) & 1) * 16;

    ld_chunk(0, m0, n0, sb, tid);
#pragma unroll 1
    for (int c = 0; c < 48; c++) {
        if (c + 1 < 48) {
            ld_chunk(c + 1, m0, n0, sb, tid);
            asm volatile("cp.async.wait_group 1;" ::: "memory");
        } else {
            asm volatile("cp.async.wait_group 0;" ::: "memory");
        }
        __syncthreads();
        uint32_t bufA = sb + (c & 1) * CH_BYTES;
        uint32_t bufB = bufA + 10240;
#pragma unroll
        for (int ks = 0; ks < 2; ks++) {
            uint32_t afr[4][4], bfr[2][4];
#pragma unroll
            for (int mt = 0; mt < 4; mt++)
                ldm4(afr[mt][0], afr[mt][1], afr[mt][2], afr[mt][3],
                     bufA + (wm * 64 + mt * 16 + a_row) * 80 + ks * 32 + a_kb);
#pragma unroll
            for (int p = 0; p < 2; p++)
                ldm4(bfr[p][0], bfr[p][1], bfr[p][2], bfr[p][3],
                     bufB + (wn * 32 + p * 16 + b_row) * 80 + ks * 32 + b_kb);
#pragma unroll
            for (int mt = 0; mt < 4; mt++)
#pragma unroll
                for (int nt = 0; nt < 4; nt++)
                    mma16816(acc[mt][nt], afr[mt], &bfr[nt >> 1][(nt & 1) * 2]);
        }
        __syncthreads();
    }

    // Epilogue: stage halves through SMEM, coalesced fp32 stores * -20
    float* stg = reinterpret_cast<float*>(smem);
#pragma unroll 1
    for (int h = 0; h < 2; h++) {
        if (wm == h) {
#pragma unroll
            for (int mt = 0; mt < 4; mt++)
#pragma unroll
                for (int nt = 0; nt < 4; nt++) {
                    int r0 = mt * 16 + (lane >> 2);
                    int cc = wn * 32 + nt * 8 + (lane & 3) * 2;
                    stg[r0 * 132 + cc]           = acc[mt][nt][0];
                    stg[r0 * 132 + cc + 1]       = acc[mt][nt][1];
                    stg[(r0 + 8) * 132 + cc]     = acc[mt][nt][2];
                    stg[(r0 + 8) * 132 + cc + 1] = acc[mt][nt][3];
                }
        }
        __syncthreads();
#pragma unroll
        for (int it = 0; it < 8; it++) {
            int idx = it * 256 + tid;
            int r = idx >> 5, c4 = idx & 31;
            float4 v = *reinterpret_cast<const float4*>(stg + r * 132 + c4 * 4);
            v.x *= -20.f; v.y *= -20.f; v.z *= -20.f; v.w *= -20.f;
            *reinterpret_cast<float4*>(
                g_M + (size_t)(m0 + h * 64 + r) * kNT + n0 + c4 * 4) = v;
        }
        __syncthreads();
    }
}

// ---------------- logits / softmax / g init ----------------
__global__ void logits_kernel(const float* __restrict__ W2, const float* __restrict__ b2)
{
    int warp = threadIdx.x >> 5, lane = threadIdx.x & 31;
    int i = blockIdx.x * 8 + warp;
    const float* hr = g_h + (size_t)i * kH;
    float acc = 0.f;
#pragma unroll
    for (int d = lane; d < kH; d += 32) acc += hr[d] * W2[d];
#pragma unroll
    for (int off = 16; off; off >>= 1) acc += __shfl_down_sync(0xffffffffu, acc, off);
    if (lane == 0) g_logits[i] = acc + b2[0];
}

__global__ void softmax_log_kernel()
{
    __shared__ float red[1024];
    int t = threadIdx.x;
    float m = NEGINF;
    for (int i = t; i < kNA; i += 1024) m = fmaxf(m, g_logits[i]);
    red[t] = m; __syncthreads();
    for (int off = 512; off; off >>= 1) {
        if (t < off) red[t] = fmaxf(red[t], red[t + off]);
        __syncthreads();
    }
    float gm = red[0]; __syncthreads();
    float sum = 0.f;
    for (int i = t; i < kNA; i += 1024) sum += __expf(g_logits[i] - gm);
    red[t] = sum; __syncthreads();
    for (int off = 512; off; off >>= 1) {
        if (t < off) red[t] += red[t + off];
        __syncthreads();
    }
    float lse = gm + logf(red[0]);
    for (int i = t; i < kNA; i += 1024) g_logb[i] = g_logits[i] - lse;
}

__global__ void ginit_kernel()
{
    int warp = threadIdx.x >> 5, lane = threadIdx.x & 31;
    int j = blockIdx.x * 8 + warp;
    const float* kr = g_k + (size_t)j * kD;
    float acc = 0.f;
#pragma unroll
    for (int d = lane; d < kD; d += 32) { float v = kr[d]; acc += v * v; }
#pragma unroll
    for (int off = 16; off; off >>= 1) acc += __shfl_down_sync(0xffffffffu, acc, off);
    if (lane == 0) g_g[j] = INV_EPS * acc;
}

// ---------------- row LSE: 4 rows/block, ascending rows ----------------
__global__ void __launch_bounds__(256) row_lse_kernel()
{
    const int i0 = blockIdx.x * 4;
    const int t = threadIdx.x;
    float m[4], s[4];
#pragma unroll
    for (int r = 0; r < 4; r++) { m[r] = NEGINF; s[r] = 0.f; }
#pragma unroll 1
    for (int c = 0; c < 4; c++) {
        const int p = c * 512 + t * 2;       // float4-pair index
        float4 ga = reinterpret_cast<const float4*>(g_g)[p];
        float4 gb = reinterpret_cast<const float4*>(g_g)[p + 1];
#pragma unroll
        for (int r = 0; r < 4; r++) {
            const float* rp = g_M + (size_t)(i0 + r) * kNT + p * 4;
            float4 ma = *reinterpret_cast<const float4*>(rp);
            float4 mb = *reinterpret_cast<const float4*>(rp + 4);
            float x0 = ma.x + ga.x, x1 = ma.y + ga.y, x2 = ma.z + ga.z, x3 = ma.w + ga.w;
            float x4 = mb.x + gb.x, x5 = mb.y + gb.y, x6 = mb.z + gb.z, x7 = mb.w + gb.w;
            float lm = fmaxf(fmaxf(fmaxf(x0, x1), fmaxf(x2, x3)),
                             fmaxf(fmaxf(x4, x5), fmaxf(x6, x7)));
            float mn = fmaxf(m[r], lm);
            float a = __expf(x0 - mn) + __expf(x1 - mn) + __expf(x2 - mn) + __expf(x3 - mn)
                    + __expf(x4 - mn) + __expf(x5 - mn) + __expf(x6 - mn) + __expf(x7 - mn);
            s[r] = s[r] * __expf(m[r] - mn) + a;
            m[r] = mn;
        }
    }
    __shared__ float sm[256], ss[256];
#pragma unroll 1
    for (int r = 0; r < 4; r++) {
        sm[t] = m[r]; ss[t] = s[r];
        __syncthreads();
        for (int off = 128; off; off >>= 1) {
            if (t < off) {
                float m2 = sm[t + off];
                float mn = fmaxf(sm[t], m2);
                ss[t] = ss[t] * __expf(sm[t] - mn) + ss[t + off] * __expf(m2 - mn);
                sm[t] = mn;
            }
            __syncthreads();
        }
        if (t == 0) g_f[i0 + r] = g_logb[i0 + r] - (sm[0] + logf(ss[0]));
        __syncthreads();
    }
}

// ---------------- column LSE: 2 cols/thread, DESCENDING segments (zigzag),
//                  fused last-block combine ----------------
__global__ void __launch_bounds__(256) col_lse_kernel(float log_a)
{
    const int t = threadIdx.x;
    const int j0 = (blockIdx.x * 256 + t) * 2;
    const int seg = 31 - blockIdx.y;          // zigzag: start where row pass ended
    const int r0 = seg * 256;
    __shared__ float fs[256];
    fs[t] = g_f[r0 + t];
    __syncthreads();
    const float* p = g_M + (size_t)r0 * kNT + j0;
    float mA = NEGINF, sA = 0.f, mB = NEGINF, sB = 0.f;
#pragma unroll 1
    for (int rb = 0; rb < 256; rb += 8) {
        float xa[8], xb[8];
#pragma unroll
        for (int r = 0; r < 8; r++) {
            float2 v = *reinterpret_cast<const float2*>(p + (size_t)(rb + r) * kNT);
            float fv = fs[rb + r];
            xa[r] = v.x + fv;
            xb[r] = v.y + fv;
        }
        float lmA = xa[0], lmB = xb[0];
#pragma unroll
        for (int r = 1; r < 8; r++) { lmA = fmaxf(lmA, xa[r]); lmB = fmaxf(lmB, xb[r]); }
        float mnA = fmaxf(mA, lmA), mnB = fmaxf(mB, lmB);
        float aA = 0.f, aB = 0.f;
#pragma unroll
        for (int r = 0; r < 8; r++) {
            aA += __expf(xa[r] - mnA);
            aB += __expf(xb[r] - mnB);
        }
        sA = sA * __expf(mA - mnA) + aA; mA = mnA;
        sB = sB * __expf(mB - mnB) + aB; mB = mnB;
    }
    *reinterpret_cast<float2*>(g_pm + (size_t)seg * kNT + j0) = make_float2(mA, mB);
    *reinterpret_cast<float2*>(g_ps + (size_t)seg * kNT + j0) = make_float2(sA, sB);

    __threadfence();
    __syncthreads();
    __shared__ int isLast;
    if (t == 0) {
        int d = atomicAdd(&g_cnt[blockIdx.x], 1);
        isLast = (d == 31);
    }
    __syncthreads();
    if (isLast) {
        __threadfence();
        float m2a = NEGINF, m2b = NEGINF;
#pragma unroll
        for (int sg = 0; sg < 32; sg++) {
            float2 v = *reinterpret_cast<const float2*>(g_pm + (size_t)sg * kNT + j0);
            m2a = fmaxf(m2a, v.x); m2b = fmaxf(m2b, v.y);
        }
        float s2a = 0.f, s2b = 0.f;
#pragma unroll
        for (int sg = 0; sg < 32; sg++) {
            float2 vm = *reinterpret_cast<const float2*>(g_pm + (size_t)sg * kNT + j0);
            float2 vs = *reinterpret_cast<const float2*>(g_ps + (size_t)sg * kNT + j0);
            s2a += vs.x * __expf(vm.x - m2a);
            s2b += vs.y * __expf(vm.y - m2b);
        }
        float2 go;
        go.x = log_a - (m2a + logf(s2a));
        go.y = log_a - (m2b + logf(s2b));
        *reinterpret_cast<float2*>(g_g + j0) = go;
        __syncthreads();
        if (t == 0) g_cnt[blockIdx.x] = 0;   // graph-replay-safe reset
    }
}

// ---------------- final T ----------------
__global__ void __launch_bounds__(256) final_T_kernel(float* __restrict__ out, float inv_total)
{
    int i = blockIdx.y;
    int pp = blockIdx.x * 256 + threadIdx.x;   // float4 index
    float fi = g_f[i];
    float4 mv = reinterpret_cast<const float4*>(g_M + (size_t)i * kNT)[pp];
    float4 gv = reinterpret_cast<const float4*>(g_g)[pp];
    float4 o;
    o.x = __expf((fi + gv.x) + mv.x) * inv_total;
    o.y = __expf((fi + gv.y) + mv.y) * inv_total;
    o.z = __expf((fi + gv.z) + mv.z) * inv_total;
    o.w = __expf((fi + gv.w) + mv.w) * inv_total;
    reinterpret_cast<float4*>(out + (size_t)i * kNT)[pp] = o;
}

// ---------------- host ----------------
extern "C" void kernel_launch(void* const* d_in, const int* in_sizes, int n_in,
                              void* d_out, int out_size)
{
    const float* Aemb = (const float*)d_in[0];
    const float* Temb = (const float*)d_in[1];
    const float* Wq   = (const float*)d_in[2];
    const float* bq   = (const float*)d_in[3];
    const float* Wk   = (const float*)d_in[4];
    const float* bk   = (const float*)d_in[5];
    const float* W1   = (const float*)d_in[6];
    const float* b1   = (const float*)d_in[7];
    const float* W2   = (const float*)d_in[8];
    const float* b2   = (const float*)d_in[9];
    float* out = (float*)d_out;

    float *pq, *pk, *ph;
    __nv_bfloat16 *pqs, *pks;
    cudaGetSymbolAddress((void**)&pq, g_q);
    cudaGetSymbolAddress((void**)&pk, g_k);
    cudaGetSymbolAddress((void**)&ph, g_h);
    cudaGetSymbolAddress((void**)&pqs, g_qs);
    cudaGetSymbolAddress((void**)&pks, g_ks);

    gemm128_kernel<false><<<dim3(2, 64), 256>>>(Aemb, Wq, bq, pq, 256, 256);
    gemm128_kernel<false><<<dim3(2, 64), 256>>>(Temb, Wk, bk, pk, 256, 256);
    gemm128_kernel<true ><<<dim3(1, 64), 256>>>(Aemb, W1, b1, ph, 128, 256);
    logits_kernel<<<1024, 256>>>(W2, b2);
    softmax_log_kernel<<<1, 1024>>>();
    ginit_kernel<<<1024, 256>>>();

    split3_kernel<<<2048, 256>>>(pq, pqs, pqs + kNA * kD, pqs + 2 * kNA * kD);
    split3_kernel<<<2048, 256>>>(pk, pks, pks + kNT * kD, pks + 2 * kNT * kD);

    mgemm_kernel<<<dim3(64, 64), 256, MG_SMEM>>>();

    const float log_a = logf(1.0f / 8192.0f + 1e-20f);
    for (int it = 0; it < 50; it++) {
        row_lse_kernel<<<2048, 256>>>();
        col_lse_kernel<<<dim3(16, 32), 256>>>(log_a);
    }
    final_T_kernel<<<dim3(8, 8192), 256>>>(out, 1.0f / (1.0f + 1e-8f));
}

// round 12
// speedup vs baseline: 1.5401x; 1.1312x over previous
#include <cuda_runtime.h>
#include <cuda_bf16.h>
#include <math.h>
#include <stdint.h>

#define kNA 8192
#define kNT 8192
#define kD  256
#define kH  128
#define kSeg 32
#define kSegRows 256
#define INV_EPS 10.0f
#define NEGINF -3.402823466e38f

__device__ float g_q[kNA * kD];
__device__ float g_k[kNT * kD];
__device__ float g_h[kNA * kH];
__device__ float g_logits[kNA];
__device__ float g_logb[kNA];
__device__ float g_f[kNA];
__device__ float g_g[kNT];
__device__ float g_M[67108864];
__device__ float g_pm[kSeg * kNT];
__device__ float g_ps[kSeg * kNT];
__device__ __nv_bfloat16 g_qs[2][kNA * kD];   // hi, lo split of q
__device__ __nv_bfloat16 g_ks[2][kNT * kD];   // hi, lo split of k

// ---------------- helpers ----------------
__device__ __forceinline__ uint32_t smem_u32(const void* p) {
    uint32_t a;
    asm("{ .reg .u64 t; cvta.to.shared.u64 t, %1; cvt.u32.u64 %0, t; }" : "=r"(a) : "l"(p));
    return a;
}
__device__ __forceinline__ void cp16(uint32_t s, const void* g) {
    asm volatile("cp.async.cg.shared.global [%0], [%1], 16;" :: "r"(s), "l"(g));
}
__device__ __forceinline__ void ldm4(uint32_t& r0, uint32_t& r1, uint32_t& r2,
                                     uint32_t& r3, uint32_t a) {
    asm volatile("ldmatrix.sync.aligned.m8n8.x4.shared.b16 {%0,%1,%2,%3}, [%4];"
                 : "=r"(r0), "=r"(r1), "=r"(r2), "=r"(r3) : "r"(a));
}
__device__ __forceinline__ void mma16816(float* c, const uint32_t* a, const uint32_t* b) {
    asm volatile("mma.sync.aligned.m16n8k16.row.col.f32.bf16.bf16.f32 "
                 "{%0,%1,%2,%3}, {%4,%5,%6,%7}, {%8,%9}, {%0,%1,%2,%3};"
                 : "+f"(c[0]), "+f"(c[1]), "+f"(c[2]), "+f"(c[3])
                 : "r"(a[0]), "r"(a[1]), "r"(a[2]), "r"(a[3]), "r"(b[0]), "r"(b[1]));
}

// ---------------- small SIMT GEMM (q,k,h) ----------------
template<bool RELU>
__global__ void __launch_bounds__(256, 2) gemm128_kernel(
    const float* __restrict__ A, const float* __restrict__ B,
    const float* __restrict__ bias, float* __restrict__ C, int N, int K)
{
    __shared__ float As[16][130];
    __shared__ float Bs[16][130];
    const int tid = threadIdx.x, tx = tid & 15, ty = tid >> 4;
    const int m0 = blockIdx.y * 128, n0 = blockIdx.x * 128;
    const int lr = tid >> 2, lk = (tid & 3) << 2;
    float acc[8][8];
#pragma unroll
    for (int i = 0; i < 8; i++)
#pragma unroll
        for (int j = 0; j < 8; j++) acc[i][j] = 0.f;
    for (int k0 = 0; k0 < K; k0 += 16) {
#pragma unroll
        for (int h = 0; h < 2; h++) {
            int row = lr + h * 64;
            float4 v = *reinterpret_cast<const float4*>(A + (size_t)(m0 + row) * K + k0 + lk);
            As[lk + 0][row] = v.x; As[lk + 1][row] = v.y;
            As[lk + 2][row] = v.z; As[lk + 3][row] = v.w;
        }
        {
            int kk = tid >> 4, nx = (tid & 15) << 2;
#pragma unroll
            for (int h = 0; h < 2; h++) {
                int n = nx + h * 64;
                float4 v = *reinterpret_cast<const float4*>(B + (size_t)(k0 + kk) * N + n0 + n);
                Bs[kk][n + 0] = v.x; Bs[kk][n + 1] = v.y;
                Bs[kk][n + 2] = v.z; Bs[kk][n + 3] = v.w;
            }
        }
        __syncthreads();
#pragma unroll
        for (int kk = 0; kk < 16; kk++) {
            float a[8], b[8];
#pragma unroll
            for (int e = 0; e < 4; e++) {
                a[e] = As[kk][ty * 4 + e];     a[e + 4] = As[kk][ty * 4 + 64 + e];
                b[e] = Bs[kk][tx * 4 + e];     b[e + 4] = Bs[kk][tx * 4 + 64 + e];
            }
#pragma unroll
            for (int i = 0; i < 8; i++)
#pragma unroll
                for (int j = 0; j < 8; j++) acc[i][j] += a[i] * b[j];
        }
        __syncthreads();
    }
#pragma unroll
    for (int i = 0; i < 8; i++) {
        int row = m0 + ty * 4 + (i < 4 ? i : i - 4 + 64);
#pragma unroll
        for (int jh = 0; jh < 2; jh++) {
            int col = n0 + tx * 4 + jh * 64;
            float4 v;
            v.x = acc[i][jh * 4 + 0] + bias[col + 0];
            v.y = acc[i][jh * 4 + 1] + bias[col + 1];
            v.z = acc[i][jh * 4 + 2] + bias[col + 2];
            v.w = acc[i][jh * 4 + 3] + bias[col + 3];
            if (RELU) {
                v.x = fmaxf(v.x, 0.f); v.y = fmaxf(v.y, 0.f);
                v.z = fmaxf(v.z, 0.f); v.w = fmaxf(v.w, 0.f);
            }
            *reinterpret_cast<float4*>(C + (size_t)row * N + col) = v;
        }
    }
}

// ---------------- bf16x2 split (hi + lo) ----------------
__global__ void __launch_bounds__(256) split2_kernel(
    const float* __restrict__ x, __nv_bfloat16* __restrict__ h0,
    __nv_bfloat16* __restrict__ l0)
{
    int i = (blockIdx.x * 256 + threadIdx.x) * 4;
    float4 v = *reinterpret_cast<const float4*>(x + i);
    float vs[4] = {v.x, v.y, v.z, v.w};
    __nv_bfloat16 hh[4], ll[4];
#pragma unroll
    for (int c = 0; c < 4; c++) {
        __nv_bfloat16 h = __float2bfloat16(vs[c]);
        float r = vs[c] - __bfloat162float(h);
        hh[c] = h; ll[c] = __float2bfloat16(r);
    }
    *reinterpret_cast<__nv_bfloat162*>(h0 + i)     = __nv_bfloat162{hh[0], hh[1]};
    *reinterpret_cast<__nv_bfloat162*>(h0 + i + 2) = __nv_bfloat162{hh[2], hh[3]};
    *reinterpret_cast<__nv_bfloat162*>(l0 + i)     = __nv_bfloat162{ll[0], ll[1]};
    *reinterpret_cast<__nv_bfloat162*>(l0 + i + 2) = __nv_bfloat162{ll[2], ll[3]};
}

// ---------------- mma.sync GEMM: M = -20 q k^T (bf16x2, 4 terms) -----------
// CTA 128x128, 8 warps (2m x 4n), warp tile 64x32. 32 chunks of K=32
// (4 terms x 8). Double-buffered cp.async, 80B-padded rows.
#define CH_BYTES 20480
#define MG_SMEM  40960

__device__ __forceinline__ void ld_chunk(int c, int m0, int n0, uint32_t sb, int tid)
{
    int term = c >> 3, kc = (c & 7) * 32;
    int at = term >> 1;          // {0,0,1,1}
    int bt = term & 1;           // {0,1,0,1}
    const __nv_bfloat16* A = &g_qs[at][0] + (size_t)m0 * kD + kc;
    const __nv_bfloat16* B = &g_ks[bt][0] + (size_t)n0 * kD + kc;
    uint32_t base = sb + (c & 1) * CH_BYTES;
#pragma unroll
    for (int i = 0; i < 4; i++) {
        int idx = i * 256 + tid;
        int mat = idx >> 9, j = idx & 511;
        int row = j >> 2, seg = j & 3;
        const __nv_bfloat16* src = (mat ? B : A) + (size_t)row * kD + seg * 8;
        cp16(base + mat * 10240 + row * 80 + seg * 16, src);
    }
    asm volatile("cp.async.commit_group;" ::: "memory");
}

__global__ void __launch_bounds__(256) mgemm_kernel()
{
    extern __shared__ char smem[];
    uint32_t sb = smem_u32(smem);
    const int tid = threadIdx.x, wid = tid >> 5, lane = tid & 31;
    const int wm = wid & 1, wn = wid >> 1;
    const int m0 = blockIdx.y * 128, n0 = blockIdx.x * 128;

    float acc[4][4][4];
#pragma unroll
    for (int i = 0; i < 4; i++)
#pragma unroll
        for (int j = 0; j < 4; j++)
#pragma unroll
            for (int e = 0; e < 4; e++) acc[i][j][e] = 0.f;

    const int a_row = lane & 15;
    const int a_kb  = (lane >> 4) * 16;
    const int b_row = (lane & 7) + ((lane >> 4) << 3);
    const int b_kb  = ((lane >> 3) & 1) * 16;

    ld_chunk(0, m0, n0, sb, tid);
#pragma unroll 1
    for (int c = 0; c < 32; c++) {
        if (c + 1 < 32) {
            ld_chunk(c + 1, m0, n0, sb, tid);
            asm volatile("cp.async.wait_group 1;" ::: "memory");
        } else {
            asm volatile("cp.async.wait_group 0;" ::: "memory");
        }
        __syncthreads();
        uint32_t bufA = sb + (c & 1) * CH_BYTES;
        uint32_t bufB = bufA + 10240;
#pragma unroll
        for (int ks = 0; ks < 2; ks++) {
            uint32_t afr[4][4], bfr[2][4];
#pragma unroll
            for (int mt = 0; mt < 4; mt++)
                ldm4(afr[mt][0], afr[mt][1], afr[mt][2], afr[mt][3],
                     bufA + (wm * 64 + mt * 16 + a_row) * 80 + ks * 32 + a_kb);
#pragma unroll
            for (int p = 0; p < 2; p++)
                ldm4(bfr[p][0], bfr[p][1], bfr[p][2], bfr[p][3],
                     bufB + (wn * 32 + p * 16 + b_row) * 80 + ks * 32 + b_kb);
#pragma unroll
            for (int mt = 0; mt < 4; mt++)
#pragma unroll
                for (int nt = 0; nt < 4; nt++)
                    mma16816(acc[mt][nt], afr[mt], &bfr[nt >> 1][(nt & 1) * 2]);
        }
        __syncthreads();
    }

    // Epilogue: stage halves through SMEM, coalesced fp32 stores * -20
    float* stg = reinterpret_cast<float*>(smem);
#pragma unroll 1
    for (int h = 0; h < 2; h++) {
        if (wm == h) {
#pragma unroll
            for (int mt = 0; mt < 4; mt++)
#pragma unroll
                for (int nt = 0; nt < 4; nt++) {
                    int r0 = mt * 16 + (lane >> 2);
                    int cc = wn * 32 + nt * 8 + (lane & 3) * 2;
                    stg[r0 * 132 + cc]           = acc[mt][nt][0];
                    stg[r0 * 132 + cc + 1]       = acc[mt][nt][1];
                    stg[(r0 + 8) * 132 + cc]     = acc[mt][nt][2];
                    stg[(r0 + 8) * 132 + cc + 1] = acc[mt][nt][3];
                }
        }
        __syncthreads();
#pragma unroll
        for (int it = 0; it < 8; it++) {
            int idx = it * 256 + tid;
            int r = idx >> 5, c4 = idx & 31;
            float4 v = *reinterpret_cast<const float4*>(stg + r * 132 + c4 * 4);
            v.x *= -20.f; v.y *= -20.f; v.z *= -20.f; v.w *= -20.f;
            *reinterpret_cast<float4*>(
                g_M + (size_t)(m0 + h * 64 + r) * kNT + n0 + c4 * 4) = v;
        }
        __syncthreads();
    }
}

// ---------------- logits / softmax / g init ----------------
__global__ void logits_kernel(const float* __restrict__ W2, const float* __restrict__ b2)
{
    int warp = threadIdx.x >> 5, lane = threadIdx.x & 31;
    int i = blockIdx.x * 8 + warp;
    const float* hr = g_h + (size_t)i * kH;
    float acc = 0.f;
#pragma unroll
    for (int d = lane; d < kH; d += 32) acc += hr[d] * W2[d];
#pragma unroll
    for (int off = 16; off; off >>= 1) acc += __shfl_down_sync(0xffffffffu, acc, off);
    if (lane == 0) g_logits[i] = acc + b2[0];
}

__global__ void softmax_log_kernel()
{
    __shared__ float red[1024];
    int t = threadIdx.x;
    float m = NEGINF;
    for (int i = t; i < kNA; i += 1024) m = fmaxf(m, g_logits[i]);
    red[t] = m; __syncthreads();
    for (int off = 512; off; off >>= 1) {
        if (t < off) red[t] = fmaxf(red[t], red[t + off]);
        __syncthreads();
    }
    float gm = red[0]; __syncthreads();
    float sum = 0.f;
    for (int i = t; i < kNA; i += 1024) sum += __expf(g_logits[i] - gm);
    red[t] = sum; __syncthreads();
    for (int off = 512; off; off >>= 1) {
        if (t < off) red[t] += red[t + off];
        __syncthreads();
    }
    float lse = gm + logf(red[0]);
    for (int i = t; i < kNA; i += 1024) g_logb[i] = g_logits[i] - lse;
}

__global__ void ginit_kernel()
{
    int warp = threadIdx.x >> 5, lane = threadIdx.x & 31;
    int j = blockIdx.x * 8 + warp;
    const float* kr = g_k + (size_t)j * kD;
    float acc = 0.f;
#pragma unroll
    for (int d = lane; d < kD; d += 32) { float v = kr[d]; acc += v * v; }
#pragma unroll
    for (int off = 16; off; off >>= 1) acc += __shfl_down_sync(0xffffffffu, acc, off);
    if (lane == 0) g_g[j] = INV_EPS * acc;
}

// ---------------- row LSE (R2-proven): 4 rows/block, float4 ----------------
__global__ void __launch_bounds__(256) row_lse_kernel()
{
    const int i0 = blockIdx.x * 4;
    const int t = threadIdx.x;
    const float4* g4 = reinterpret_cast<const float4*>(g_g);
    float m[4], s[4];
#pragma unroll
    for (int r = 0; r < 4; r++) { m[r] = NEGINF; s[r] = 0.f; }
#pragma unroll
    for (int c = 0; c < 8; c++) {
        const int p = c * 256 + t;
        float4 gv = g4[p];
#pragma unroll
        for (int r = 0; r < 4; r++) {
            float4 mv = reinterpret_cast<const float4*>(
                g_M + (size_t)(i0 + r) * kNT)[p];
            float x0 = mv.x + gv.x, x1 = mv.y + gv.y;
            float x2 = mv.z + gv.z, x3 = mv.w + gv.w;
            float lm = fmaxf(fmaxf(x0, x1), fmaxf(x2, x3));
            float mn = fmaxf(m[r], lm);
            float acc = __expf(x0 - mn) + __expf(x1 - mn)
                      + __expf(x2 - mn) + __expf(x3 - mn);
            s[r] = s[r] * __expf(m[r] - mn) + acc;
            m[r] = mn;
        }
    }
    __shared__ float sm[256], ss[256];
#pragma unroll 1
    for (int r = 0; r < 4; r++) {
        sm[t] = m[r]; ss[t] = s[r];
        __syncthreads();
        for (int off = 128; off; off >>= 1) {
            if (t < off) {
                float m2 = sm[t + off];
                float mn = fmaxf(sm[t], m2);
                ss[t] = ss[t] * __expf(sm[t] - mn) + ss[t + off] * __expf(m2 - mn);
                sm[t] = mn;
            }
            __syncthreads();
        }
        if (t == 0) g_f[i0 + r] = g_logb[i0 + r] - (sm[0] + logf(ss[0]));
        __syncthreads();
    }
}

// ---------------- column LSE (R2-proven): 1 col/thread, scalar ----------------
__global__ void __launch_bounds__(256) col_lse_kernel()
{
    const int j = blockIdx.x * 256 + threadIdx.x;
    const int seg = blockIdx.y;
    const int r0 = seg * kSegRows;
    __shared__ float fs[kSegRows];
    fs[threadIdx.x] = g_f[r0 + threadIdx.x];
    __syncthreads();
    const float* p = g_M + (size_t)r0 * kNT + j;
    float m = NEGINF, s = 0.f;
    for (int rb = 0; rb < kSegRows; rb += 8) {
        float x[8];
#pragma unroll
        for (int r = 0; r < 8; r++)
            x[r] = p[(size_t)(rb + r) * kNT] + fs[rb + r];
        float lm = x[0];
#pragma unroll
        for (int r = 1; r < 8; r++) lm = fmaxf(lm, x[r]);
        float mn = fmaxf(m, lm);
        float acc = 0.f;
#pragma unroll
        for (int r = 0; r < 8; r++) acc += __expf(x[r] - mn);
        s = s * __expf(m - mn) + acc;
        m = mn;
    }
    g_pm[seg * kNT + j] = m;
    g_ps[seg * kNT + j] = s;
}

__global__ void col_combine_kernel(float log_a)
{
    int j = blockIdx.x * 256 + threadIdx.x;
    float m = NEGINF;
#pragma unroll
    for (int sg = 0; sg < kSeg; sg++) m = fmaxf(m, g_pm[sg * kNT + j]);
    float acc = 0.f;
#pragma unroll
    for (int sg = 0; sg < kSeg; sg++)
        acc += g_ps[sg * kNT + j] * __expf(g_pm[sg * kNT + j] - m);
    g_g[j] = log_a - (m + logf(acc));
}

// ---------------- final T ----------------
__global__ void __launch_bounds__(256) final_T_kernel(float* __restrict__ out,
                                                      float inv_total)
{
    int i = blockIdx.y;
    int p = blockIdx.x * 256 + threadIdx.x;   // float4 index
    float fi = g_f[i];
    float4 mv = reinterpret_cast<const float4*>(g_M + (size_t)i * kNT)[p];
    float4 gv = reinterpret_cast<const float4*>(g_g)[p];
    float4 o;
    o.x = __expf((fi + gv.x) + mv.x) * inv_total;
    o.y = __expf((fi + gv.y) + mv.y) * inv_total;
    o.z = __expf((fi + gv.z) + mv.z) * inv_total;
    o.w = __expf((fi + gv.w) + mv.w) * inv_total;
    reinterpret_cast<float4*>(out + (size_t)i * kNT)[p] = o;
}

// ---------------- host ----------------
extern "C" void kernel_launch(void* const* d_in, const int* in_sizes, int n_in,
                              void* d_out, int out_size)
{
    const float* Aemb = (const float*)d_in[0];
    const float* Temb = (const float*)d_in[1];
    const float* Wq   = (const float*)d_in[2];
    const float* bq   = (const float*)d_in[3];
    const float* Wk   = (const float*)d_in[4];
    const float* bk   = (const float*)d_in[5];
    const float* W1   = (const float*)d_in[6];
    const float* b1   = (const float*)d_in[7];
    const float* W2   = (const float*)d_in[8];
    const float* b2   = (const float*)d_in[9];
    float* out = (float*)d_out;

    float *pq, *pk, *ph;
    __nv_bfloat16 *pqs, *pks;
    cudaGetSymbolAddress((void**)&pq, g_q);
    cudaGetSymbolAddress((void**)&pk, g_k);
    cudaGetSymbolAddress((void**)&ph, g_h);
    cudaGetSymbolAddress((void**)&pqs, g_qs);
    cudaGetSymbolAddress((void**)&pks, g_ks);

    gemm128_kernel<false><<<dim3(2, 64), 256>>>(Aemb, Wq, bq, pq, 256, 256);
    gemm128_kernel<false><<<dim3(2, 64), 256>>>(Temb, Wk, bk, pk, 256, 256);
    gemm128_kernel<true ><<<dim3(1, 64), 256>>>(Aemb, W1, b1, ph, 128, 256);
    logits_kernel<<<1024, 256>>>(W2, b2);
    softmax_log_kernel<<<1, 1024>>>();
    ginit_kernel<<<1024, 256>>>();

    split2_kernel<<<2048, 256>>>(pq, pqs, pqs + kNA * kD);
    split2_kernel<<<2048, 256>>>(pk, pks, pks + kNT * kD);

    mgemm_kernel<<<dim3(64, 64), 256, MG_SMEM>>>();

    const float log_a = logf(1.0f / 8192.0f + 1e-20f);
    for (int it = 0; it < 50; it++) {
        row_lse_kernel<<<2048, 256>>>();
        col_lse_kernel<<<dim3(32, 32), 256>>>();
        col_combine_kernel<<<32, 256>>>(log_a);
    }
    final_T_kernel<<<dim3(8, 8192), 256>>>(out, 1.0f / (1.0f + 1e-8f));
}